// round 16
// baseline (speedup 1.0000x reference)
#include <cuda_runtime.h>
#include <cuda_fp16.h>
#include <math.h>
#include <stdint.h>

// Problem constants (fixed by the reference)
#define NB 4
#define LQ 5440
#define LV 5440
#define CD 256
#define NH 8
#define HD 32
#define MROWS (NB * LQ)   // 21760
#define NFUSE 384

// Scratch (device globals: no allocation allowed in kernel_launch)
// vproj in HEAD-MAJOR fp16 layout: [b][h][lv][32] (+pad for edge overreads)
__device__ __half g_vprojH [(size_t)MROWS * CD + 64];
__device__ float  g_offattn[(size_t)MROWS * NFUSE];  // fused proj output (fp32)
__device__ __half g_qH  [(size_t)MROWS * CD];        // query in fp16
__device__ __half g_vH  [(size_t)MROWS * CD];        // value in fp16
__device__ __half g_accH[(size_t)MROWS * CD];        // sampler output in fp16
__device__ float  g_bf  [NFUSE];
// Weights pre-packed as fp16x2 words in m16n8k16 B-fragment order:
// [nt][stage(8)][2048 words]
__device__ uint32_t g_BpV[2 * 8 * 2048];
__device__ uint32_t g_BpF[3 * 8 * 2048];
__device__ uint32_t g_BpO[2 * 8 * 2048];

// ---------------------------------------------------------------------------
__device__ __forceinline__ uint32_t smem_u32(const void* p) {
    uint32_t a;
    asm("{ .reg .u64 t; cvta.to.shared.u64 t, %1; cvt.u32.u64 %0, t; }" : "=r"(a) : "l"(p));
    return a;
}

__device__ __forceinline__ void cp_async16(uint32_t dst, const void* src) {
    asm volatile("cp.async.cg.shared.global [%0], [%1], 16;" :: "r"(dst), "l"(src) : "memory");
}

#define CP_COMMIT() asm volatile("cp.async.commit_group;" ::: "memory")

#define LDSM_X4(r, a) \
    asm volatile("ldmatrix.sync.aligned.m8n8.x4.shared.b16 {%0,%1,%2,%3}, [%4];" \
        : "=r"((r)[0]), "=r"((r)[1]), "=r"((r)[2]), "=r"((r)[3]) : "r"(a))

__device__ __forceinline__ void mma_f16(float* c, const unsigned* a, const unsigned* b) {
    asm volatile(
        "mma.sync.aligned.m16n8k16.row.col.f32.f16.f16.f32 "
        "{%0,%1,%2,%3}, {%4,%5,%6,%7}, {%8,%9}, {%0,%1,%2,%3};"
        : "+f"(c[0]), "+f"(c[1]), "+f"(c[2]), "+f"(c[3])
        : "r"(a[0]), "r"(a[1]), "r"(a[2]), "r"(a[3]), "r"(b[0]), "r"(b[1]));
}

__device__ __forceinline__ unsigned packh2(float x, float y) {
    __half2 h = __floats2half2_rn(x, y);
    return *(unsigned*)&h;
}

// ---------------------------------------------------------------------------
// prep: convert query & value fp32->fp16 AND pre-pack weights + bias.
// ---------------------------------------------------------------------------
#define CONV_N (2 * MROWS * 64)

__global__ void prep(const float4* __restrict__ q, const float4* __restrict__ v,
                     const float* __restrict__ W_off, const float* __restrict__ b_off,
                     const float* __restrict__ W_at,  const float* __restrict__ b_at,
                     const float* __restrict__ W_val, const float* __restrict__ W_out)
{
    const int i = blockIdx.x * 256 + threadIdx.x;
    if (i < CONV_N) {
        const float4* src;
        __half* dst;
        int idx;
        if (i < MROWS * 64) { src = q; dst = g_qH; idx = i; }
        else                { src = v; dst = g_vH; idx = i - MROWS * 64; }
        const float4 f = src[idx];
        uint2 o;
        o.x = packh2(f.x, f.y);
        o.y = packh2(f.z, f.w);
        *(uint2*)&dst[(size_t)idx * 4] = o;
        return;
    }

    const int j = i - CONV_N;
    if (j < NFUSE) g_bf[j] = (j < 256) ? b_off[j] : b_at[j - 256];
    if (j >= 114688) return;

    uint32_t* dst;
    int idx, which;                 // 0=V, 1=F, 2=O
    if (j < 32768)      { dst = g_BpV; idx = j;         which = 0; }
    else if (j < 81920) { dst = g_BpF; idx = j - 32768; which = 1; }
    else                { dst = g_BpO; idx = j - 81920; which = 2; }

    const int nt   = idx >> 14;
    const int rem  = idx & 16383;
    const int s    = rem >> 11;
    const int w    = rem & 2047;
    const int t    = w >> 6;
    const int lane = (w >> 1) & 31;
    const int reg  = w & 1;

    const int n  = (t >> 1) * 8 + (lane >> 2);
    const int k  = s * 32 + (t & 1) * 16 + (lane & 3) * 2 + 8 * reg;
    const int ng = nt * 128 + n;

    float v0, v1;
    if (which == 0)      { v0 = W_val[k * 256 + ng]; v1 = W_val[(k + 1) * 256 + ng]; }
    else if (which == 2) { v0 = W_out[k * 256 + ng]; v1 = W_out[(k + 1) * 256 + ng]; }
    else if (ng < 256)   { v0 = W_off[k * 256 + ng]; v1 = W_off[(k + 1) * 256 + ng]; }
    else                 { v0 = W_at[k * 128 + ng - 256]; v1 = W_at[(k + 1) * 128 + ng - 256]; }

    dst[idx] = packh2(v0, v1);
}

// ---------------------------------------------------------------------------
// fp16 mma.sync GEMM, MT=64, depth-4 cp.async pipeline (R11 champion
// structure). Per-job epilogue: OUT = 0 fp32 row-major; OUT = 2 fp16
// head-major via smem-staged COALESCED store (fixes 4x write amplification
// of the direct scatter).
// ---------------------------------------------------------------------------
template <int OUT0, int OUT1>
__global__ __launch_bounds__(256, 3) void gemm_f16(
    const __half* __restrict__ A0, const uint32_t* __restrict__ B0,
    const float* __restrict__ bias0, void* __restrict__ C0, int N0, int nt0,
    const __half* __restrict__ A1, const uint32_t* __restrict__ B1,
    const float* __restrict__ bias1, void* __restrict__ C1, int N1)
{
    constexpr int MT   = 64;
    constexpr int ASTG = MT * 64;            // 4096 B
    constexpr int STG  = ASTG + 8192;        // 12288 B
    __shared__ __align__(16) uint8_t sm[4][STG];   // 48 KB

    const int tid  = threadIdx.x;
    const int lane = tid & 31;
    const int warp = tid >> 5;
    const int mt   = blockIdx.y;

    const __half* A; const uint32_t* Bp; const float* bias; void* C; int N; int nt; int omode;
    if ((int)blockIdx.x < nt0) {
        A = A0; Bp = B0; bias = bias0; C = C0; N = N0; nt = blockIdx.x; omode = OUT0;
    } else {
        A = A1; Bp = B1; bias = bias1; C = C1; N = N1; nt = blockIdx.x - nt0; omode = OUT1;
    }

    const int wm = (warp >> 2) * 32;
    const int wn = (warp & 3) * 32;

    const uint32_t smb = smem_u32(sm);
    const __half* Abase = A + (size_t)(mt * MT) * 256;
    const uint32_t* Bbase = Bp + (size_t)nt * 8 * 2048;

    const int rbase = wm + (lane & 15);
    const int uoff  = lane >> 4;
    const int s3    = rbase & 3;

    auto issue = [&](int st) {
        const int slot = st & 3;
        const uint32_t smA = smb + slot * STG;
        const uint32_t smB = smA + ASTG;
        const int k0 = st * 32;
        {
            const int m = tid >> 2, u = tid & 3;
            cp_async16(smA + m * 64 + ((u ^ (m & 3)) * 16),
                       Abase + (size_t)m * 256 + k0 + u * 8);
        }
        const char* bsrc = (const char*)(Bbase + (size_t)st * 2048);
#pragma unroll
        for (int i = 0; i < 2; i++) {
            const int idx = tid + i * 256;
            cp_async16(smB + idx * 16, bsrc + (size_t)idx * 16);
        }
        CP_COMMIT();
    };

    issue(0); issue(1); issue(2);

    float acc[2][4][4] = {};

#pragma unroll 1
    for (int st = 0; st < 8; st++) {
        if (st + 3 < 8) issue(st + 3);
        if (st < 5)       asm volatile("cp.async.wait_group 3;" ::: "memory");
        else if (st == 5) asm volatile("cp.async.wait_group 2;" ::: "memory");
        else if (st == 6) asm volatile("cp.async.wait_group 1;" ::: "memory");
        else              asm volatile("cp.async.wait_group 0;" ::: "memory");
        __syncthreads();

        const int slot = st & 3;
        const uint32_t smA = smb + slot * STG;
        const uint32_t smB = smA + ASTG;

#pragma unroll
        for (int tk = 0; tk < 2; tk++) {
            unsigned af[2][4];
            const uint32_t uphys = (uint32_t)((tk * 2 + uoff) ^ s3) * 16;
#pragma unroll
            for (int tm = 0; tm < 2; tm++)
                LDSM_X4(af[tm], smA + (uint32_t)(rbase + tm * 16) * 64 + uphys);

            unsigned bf[4][2];
#pragma unroll
            for (int tn = 0; tn < 4; tn++) {
                const int widx = (((wn >> 3) + tn) * 2 + tk) * 32 + lane;
                asm("ld.shared.v2.b32 {%0,%1}, [%2];"
                    : "=r"(bf[tn][0]), "=r"(bf[tn][1]) : "r"(smB + widx * 8));
            }
#pragma unroll
            for (int mi = 0; mi < 2; mi++)
#pragma unroll
                for (int ni = 0; ni < 4; ni++)
                    mma_f16(acc[mi][ni], af[mi], bf[ni]);
        }
        __syncthreads();
    }

    if (omode == 2) {
        // --- staged head-major epilogue: smem tile [64][136 halves] then
        //     coalesced uint4 stores (64B contiguous per head-row)
        __half* stg = (__half*)sm;
#pragma unroll
        for (int mi = 0; mi < 2; mi++) {
            const int rl = wm + mi * 16 + (lane >> 2);
#pragma unroll
            for (int ni = 0; ni < 4; ni++) {
                const int cl = wn + ni * 8 + (lane & 3) * 2;
                const float2 bv = *(const float2*)&bias[nt * 128 + cl];
                *(uint32_t*)&stg[rl * 136 + cl] =
                    packh2(acc[mi][ni][0] + bv.x, acc[mi][ni][1] + bv.y);
                *(uint32_t*)&stg[(rl + 8) * 136 + cl] =
                    packh2(acc[mi][ni][2] + bv.x, acc[mi][ni][3] + bv.y);
            }
        }
        __syncthreads();

        const int rg0 = mt * MT;
        const int b   = rg0 / LQ;        // tiles never straddle batches (5440 % 64 == 0)
        const int lv0 = rg0 - b * LQ;
        __half* gb = (__half*)C;
#pragma unroll
        for (int i = 0; i < 4; i++) {
            const int seg = tid + i * 256;         // 1024 segs of 16B
            const int row = seg >> 4;
            const int sir = seg & 15;
            const int hhl = sir >> 2;              // head within tile (4 heads)
            const int ch  = (sir & 3) * 8;
            const uint4 v = *(const uint4*)&stg[row * 136 + sir * 8];
            *(uint4*)&gb[((size_t)(b * NH + nt * 4 + hhl) * LQ + lv0 + row) * 32 + ch] = v;
        }
    } else {
#pragma unroll
        for (int mi = 0; mi < 2; mi++) {
            const int r = mt * MT + wm + mi * 16 + (lane >> 2);
#pragma unroll
            for (int ni = 0; ni < 4; ni++) {
                const int c = nt * 128 + wn + ni * 8 + (lane & 3) * 2;
                const float2 bv = *(const float2*)&bias[c];
                float* CF = (float*)C;
                *(float2*)&CF[(size_t)r * N + c] =
                    make_float2(acc[mi][ni][0] + bv.x, acc[mi][ni][1] + bv.y);
                *(float2*)&CF[(size_t)(r + 8) * N + c] =
                    make_float2(acc[mi][ni][2] + bv.x, acc[mi][ni][3] + bv.y);
            }
        }
    }
}

// ---------------------------------------------------------------------------
// Deformable sampling — warp = (query, head-pair). Lanes 0-15 build head h0's
// taps, lanes 16-31 head h1's. Taps stored TAP-MAJOR [tap][head] so the
// gather fetches both heads' (offset, weight) with ONE LDS.128 per j.
// Gather interleaves both heads (MLP 16); folded reduction.
// ---------------------------------------------------------------------------
__global__ __launch_bounds__(256, 6) void ms_sample_kernel(
    const float* __restrict__ refp)   // [B, Lq, 4, 2]
{
    const int t    = threadIdx.x;
    const int warp = t >> 5;
    const int lid  = t & 31;
    const int qi   = blockIdx.x * 2 + (warp >> 2);
    const int b    = blockIdx.y;
    const int bq   = b * LQ + qi;
    const int wh   = warp & 3;        // head pair: heads 2*wh, 2*wh+1
    const int hw   = lid >> 4;        // which head within pair
    const int h    = wh * 2 + hw;
    const int lp   = lid & 15;        // (level, point)

    __shared__ int2 s_tap[8][64][2];  // [warp][tap][head] {byte_off, w}

    // --- fused softmax + tap build, both half-warps active
    {
        const float logit = g_offattn[(size_t)bq * NFUSE + 256 + h * 16 + lp];
        float m = logit;
#pragma unroll
        for (int o = 8; o; o >>= 1) m = fmaxf(m, __shfl_xor_sync(0xFFFFFFFFu, m, o));
        const float e = __expf(logit - m);
        float ssum = e;
#pragma unroll
        for (int o = 8; o; o >>= 1) ssum += __shfl_xor_sync(0xFFFFFFFFu, ssum, o);
        const float aw = e / ssum;

        const int l = lp >> 2;
        const int W = 64 >> l;
        const int start = (l == 0) ? 0 : (l == 1) ? 4096 : (l == 2) ? 5120 : 5376;

        const float rx = refp[((size_t)bq * 4 + l) * 2 + 0];
        const float ry = refp[((size_t)bq * 4 + l) * 2 + 1];
        const float* op = g_offattn + (size_t)bq * NFUSE + h * 32 + lp * 2;

        const float x = fmaf(rx, (float)W, op[0]) - 0.5f;
        const float y = fmaf(ry, (float)W, op[1]) - 0.5f;
        const float x0f = floorf(x), y0f = floorf(y);
        const int x0 = (int)x0f, y0 = (int)y0f;
        const float wx = x - x0f, wy = y - y0f;

        const bool xi0 = (x0 >= 0) && (x0 < W);
        const bool xi1 = (x0 + 1 >= 0) && (x0 + 1 < W);
        const bool yi0 = (y0 >= 0) && (y0 < W);
        const bool yi1 = (y0 + 1 >= 0) && (y0 + 1 < W);

        const int base = (start + y0 * W + x0) * 64;   // byte offset (64B/row)
        const int wb   = W * 64;
        bool v;
        v = xi0 && yi0;
        s_tap[warp][lp * 4 + 0][hw] =
            make_int2(v ? base : 0,           __float_as_int(v ? aw * (1.f - wx) * (1.f - wy) : 0.f));
        v = xi1 && yi0;
        s_tap[warp][lp * 4 + 1][hw] =
            make_int2(v ? base + 64 : 0,      __float_as_int(v ? aw * wx * (1.f - wy) : 0.f));
        v = xi0 && yi1;
        s_tap[warp][lp * 4 + 2][hw] =
            make_int2(v ? base + wb : 0,      __float_as_int(v ? aw * (1.f - wx) * wy : 0.f));
        v = xi1 && yi1;
        s_tap[warp][lp * 4 + 3][hw] =
            make_int2(v ? base + wb + 64 : 0, __float_as_int(v ? aw * wx * wy : 0.f));
    }
    __syncwarp();

    // --- interleaved gather for both heads (sub-slot = lid>>2: 8 taps/instr)
    const int sub = lid >> 2;
    const int cb  = (lid & 3) * 16;   // byte offset of channel octet
    const char* vb0 = (const char*)(g_vprojH + ((size_t)(b * NH + wh * 2) * LQ) * 32) + cb;
    const char* vb1 = vb0 + (size_t)LQ * 64;
    const int4* tp = (const int4*)s_tap[warp];

    float a[8] = {}, c[8] = {};
#pragma unroll
    for (int j = 0; j < 8; j++) {
        const int4 tv = tp[j * 8 + sub];     // {off0, w0, off1, w1}
        const float w0 = __int_as_float(tv.y);
        const float w1 = __int_as_float(tv.w);
        const uint4 v0 = *(const uint4*)(vb0 + tv.x);
        const uint4 v1 = *(const uint4*)(vb1 + tv.z);
        const float2 p0 = __half22float2(*(const __half2*)&v0.x);
        const float2 p1 = __half22float2(*(const __half2*)&v0.y);
        const float2 p2 = __half22float2(*(const __half2*)&v0.z);
        const float2 p3 = __half22float2(*(const __half2*)&v0.w);
        a[0] = fmaf(w0, p0.x, a[0]); a[1] = fmaf(w0, p0.y, a[1]);
        a[2] = fmaf(w0, p1.x, a[2]); a[3] = fmaf(w0, p1.y, a[3]);
        a[4] = fmaf(w0, p2.x, a[4]); a[5] = fmaf(w0, p2.y, a[5]);
        a[6] = fmaf(w0, p3.x, a[6]); a[7] = fmaf(w0, p3.y, a[7]);
        const float2 q0 = __half22float2(*(const __half2*)&v1.x);
        const float2 q1 = __half22float2(*(const __half2*)&v1.y);
        const float2 q2 = __half22float2(*(const __half2*)&v1.z);
        const float2 q3 = __half22float2(*(const __half2*)&v1.w);
        c[0] = fmaf(w1, q0.x, c[0]); c[1] = fmaf(w1, q0.y, c[1]);
        c[2] = fmaf(w1, q1.x, c[2]); c[3] = fmaf(w1, q1.y, c[3]);
        c[4] = fmaf(w1, q2.x, c[4]); c[5] = fmaf(w1, q2.y, c[5]);
        c[6] = fmaf(w1, q3.x, c[6]); c[7] = fmaf(w1, q3.y, c[7]);
    }

    // fold head dim into lane bit4, then reduce strides 4, 8
#pragma unroll
    for (int k = 0; k < 8; k++) {
        const float ax = a[k] + __shfl_xor_sync(0xFFFFFFFFu, a[k], 16);
        const float cx = c[k] + __shfl_xor_sync(0xFFFFFFFFu, c[k], 16);
        a[k] = (lid < 16) ? ax : cx;
    }
#pragma unroll
    for (int o = 4; o <= 8; o <<= 1)
#pragma unroll
        for (int k = 0; k < 8; k++)
            a[k] += __shfl_xor_sync(0xFFFFFFFFu, a[k], o);

    if ((lid & 12) == 0) {
        const int hcur = wh * 2 + (lid >> 4);
        const int ch   = (lid & 3) * 8;
        uint4 o;
        o.x = packh2(a[0], a[1]);
        o.y = packh2(a[2], a[3]);
        o.z = packh2(a[4], a[5]);
        o.w = packh2(a[6], a[7]);
        *(uint4*)&g_accH[(size_t)bq * CD + hcur * HD + ch] = o;
    }
}

// ---------------------------------------------------------------------------
// kernel_launch
// Inputs: query, reference_points, value, W_off, b_off, W_attn, b_attn,
//         W_val, b_val, W_out, b_out
// ---------------------------------------------------------------------------
extern "C" void kernel_launch(void* const* d_in, const int* in_sizes, int n_in,
                              void* d_out, int out_size)
{
    const float* query = (const float*)d_in[0];
    const float* refp  = (const float*)d_in[1];
    const float* value = (const float*)d_in[2];
    const float* W_off = (const float*)d_in[3];
    const float* b_off = (const float*)d_in[4];
    const float* W_at  = (const float*)d_in[5];
    const float* b_at  = (const float*)d_in[6];
    const float* W_val = (const float*)d_in[7];
    const float* b_val = (const float*)d_in[8];
    const float* W_out = (const float*)d_in[9];
    const float* b_out = (const float*)d_in[10];
    float* out = (float*)d_out;

    float *offattn, *bf;
    __half *vprojh, *qh, *vh, *acch;
    uint32_t *bpv, *bpf, *bpo;
    cudaGetSymbolAddress((void**)&vprojh,  g_vprojH);
    cudaGetSymbolAddress((void**)&offattn, g_offattn);
    cudaGetSymbolAddress((void**)&qh,      g_qH);
    cudaGetSymbolAddress((void**)&vh,      g_vH);
    cudaGetSymbolAddress((void**)&acch,    g_accH);
    cudaGetSymbolAddress((void**)&bf,      g_bf);
    cudaGetSymbolAddress((void**)&bpv,     g_BpV);
    cudaGetSymbolAddress((void**)&bpf,     g_BpF);
    cudaGetSymbolAddress((void**)&bpo,     g_BpO);

    dim3 blk(256);

    prep<<<(CONV_N + 114688) / 256, blk>>>((const float4*)query, (const float4*)value,
                                           W_off, b_off, W_at, b_at, W_val, W_out);
    // fused: V-proj (2 n-tiles, fp16 head-major coalesced out) + offattn-proj (3, fp32)
    gemm_f16<2, 0><<<dim3(5, MROWS / 64), blk>>>(vh, bpv, b_val, vprojh, 256, 2,
                                                 qh, bpf, bf, offattn, NFUSE);
    ms_sample_kernel<<<dim3(LQ / 2, NB), blk>>>(refp);
    gemm_f16<0, 0><<<dim3(2, MROWS / 64), blk>>>(acch, bpo, b_out, out, 256, 2,
                                                 acch, bpo, b_out, out, 256);
}

// round 17
// speedup vs baseline: 1.0952x; 1.0952x over previous
#include <cuda_runtime.h>
#include <cuda_fp16.h>
#include <math.h>
#include <stdint.h>

// Problem constants (fixed by the reference)
#define NB 4
#define LQ 5440
#define LV 5440
#define CD 256
#define NH 8
#define HD 32
#define MROWS (NB * LQ)   // 21760
#define NFUSE 384

// Scratch (device globals: no allocation allowed in kernel_launch)
// vproj in HEAD-MAJOR fp16 layout: [b][h][lv][32] (+pad for edge overreads)
__device__ __half g_vprojH [(size_t)MROWS * CD + 64];
__device__ float  g_offattn[(size_t)MROWS * NFUSE];  // fused proj output (fp32)
__device__ __half g_qH  [(size_t)MROWS * CD];        // query in fp16
__device__ __half g_vH  [(size_t)MROWS * CD];        // value in fp16
__device__ __half g_accH[(size_t)MROWS * CD];        // sampler output in fp16
__device__ float  g_bf  [NFUSE];
// Weights pre-packed as fp16x2 words in m16n8k16 B-fragment order:
// [nt][stage(8)][2048 words]
__device__ uint32_t g_BpV[2 * 8 * 2048];
__device__ uint32_t g_BpF[3 * 8 * 2048];
__device__ uint32_t g_BpO[2 * 8 * 2048];

// ---------------------------------------------------------------------------
__device__ __forceinline__ uint32_t smem_u32(const void* p) {
    uint32_t a;
    asm("{ .reg .u64 t; cvta.to.shared.u64 t, %1; cvt.u32.u64 %0, t; }" : "=r"(a) : "l"(p));
    return a;
}

__device__ __forceinline__ void cp_async16(uint32_t dst, const void* src) {
    asm volatile("cp.async.cg.shared.global [%0], [%1], 16;" :: "r"(dst), "l"(src) : "memory");
}

#define CP_COMMIT() asm volatile("cp.async.commit_group;" ::: "memory")

#define LDSM_X4(r, a) \
    asm volatile("ldmatrix.sync.aligned.m8n8.x4.shared.b16 {%0,%1,%2,%3}, [%4];" \
        : "=r"((r)[0]), "=r"((r)[1]), "=r"((r)[2]), "=r"((r)[3]) : "r"(a))

__device__ __forceinline__ void mma_f16(float* c, const unsigned* a, const unsigned* b) {
    asm volatile(
        "mma.sync.aligned.m16n8k16.row.col.f32.f16.f16.f32 "
        "{%0,%1,%2,%3}, {%4,%5,%6,%7}, {%8,%9}, {%0,%1,%2,%3};"
        : "+f"(c[0]), "+f"(c[1]), "+f"(c[2]), "+f"(c[3])
        : "r"(a[0]), "r"(a[1]), "r"(a[2]), "r"(a[3]), "r"(b[0]), "r"(b[1]));
}

__device__ __forceinline__ unsigned packh2(float x, float y) {
    __half2 h = __floats2half2_rn(x, y);
    return *(unsigned*)&h;
}

// ---------------------------------------------------------------------------
// prep: convert query & value fp32->fp16 AND pre-pack weights + bias.
// ---------------------------------------------------------------------------
#define CONV_N (2 * MROWS * 64)

__global__ void prep(const float4* __restrict__ q, const float4* __restrict__ v,
                     const float* __restrict__ W_off, const float* __restrict__ b_off,
                     const float* __restrict__ W_at,  const float* __restrict__ b_at,
                     const float* __restrict__ W_val, const float* __restrict__ W_out)
{
    const int i = blockIdx.x * 256 + threadIdx.x;
    if (i < CONV_N) {
        const float4* src;
        __half* dst;
        int idx;
        if (i < MROWS * 64) { src = q; dst = g_qH; idx = i; }
        else                { src = v; dst = g_vH; idx = i - MROWS * 64; }
        const float4 f = src[idx];
        uint2 o;
        o.x = packh2(f.x, f.y);
        o.y = packh2(f.z, f.w);
        *(uint2*)&dst[(size_t)idx * 4] = o;
        return;
    }

    const int j = i - CONV_N;
    if (j < NFUSE) g_bf[j] = (j < 256) ? b_off[j] : b_at[j - 256];
    if (j >= 114688) return;

    uint32_t* dst;
    int idx, which;                 // 0=V, 1=F, 2=O
    if (j < 32768)      { dst = g_BpV; idx = j;         which = 0; }
    else if (j < 81920) { dst = g_BpF; idx = j - 32768; which = 1; }
    else                { dst = g_BpO; idx = j - 81920; which = 2; }

    const int nt   = idx >> 14;
    const int rem  = idx & 16383;
    const int s    = rem >> 11;
    const int w    = rem & 2047;
    const int t    = w >> 6;
    const int lane = (w >> 1) & 31;
    const int reg  = w & 1;

    const int n  = (t >> 1) * 8 + (lane >> 2);
    const int k  = s * 32 + (t & 1) * 16 + (lane & 3) * 2 + 8 * reg;
    const int ng = nt * 128 + n;

    float v0, v1;
    if (which == 0)      { v0 = W_val[k * 256 + ng]; v1 = W_val[(k + 1) * 256 + ng]; }
    else if (which == 2) { v0 = W_out[k * 256 + ng]; v1 = W_out[(k + 1) * 256 + ng]; }
    else if (ng < 256)   { v0 = W_off[k * 256 + ng]; v1 = W_off[(k + 1) * 256 + ng]; }
    else                 { v0 = W_at[k * 128 + ng - 256]; v1 = W_at[(k + 1) * 128 + ng - 256]; }

    dst[idx] = packh2(v0, v1);
}

// ---------------------------------------------------------------------------
// fp16 mma.sync GEMM, MT=64, depth-4 cp.async pipeline (R11 champion).
// Per-job epilogue: OUT = 0 fp32 row-major; OUT = 2 fp16 head-major.
// ---------------------------------------------------------------------------
template <int OUT0, int OUT1>
__global__ __launch_bounds__(256, 3) void gemm_f16(
    const __half* __restrict__ A0, const uint32_t* __restrict__ B0,
    const float* __restrict__ bias0, void* __restrict__ C0, int N0, int nt0,
    const __half* __restrict__ A1, const uint32_t* __restrict__ B1,
    const float* __restrict__ bias1, void* __restrict__ C1, int N1)
{
    constexpr int MT   = 64;
    constexpr int ASTG = MT * 64;            // 4096 B
    constexpr int STG  = ASTG + 8192;        // 12288 B
    __shared__ __align__(16) uint8_t sm[4][STG];   // 48 KB

    const int tid  = threadIdx.x;
    const int lane = tid & 31;
    const int warp = tid >> 5;
    const int mt   = blockIdx.y;

    const __half* A; const uint32_t* Bp; const float* bias; void* C; int N; int nt; int omode;
    if ((int)blockIdx.x < nt0) {
        A = A0; Bp = B0; bias = bias0; C = C0; N = N0; nt = blockIdx.x; omode = OUT0;
    } else {
        A = A1; Bp = B1; bias = bias1; C = C1; N = N1; nt = blockIdx.x - nt0; omode = OUT1;
    }

    const int wm = (warp >> 2) * 32;
    const int wn = (warp & 3) * 32;

    const uint32_t smb = smem_u32(sm);
    const __half* Abase = A + (size_t)(mt * MT) * 256;
    const uint32_t* Bbase = Bp + (size_t)nt * 8 * 2048;

    const int rbase = wm + (lane & 15);
    const int uoff  = lane >> 4;
    const int s3    = rbase & 3;

    auto issue = [&](int st) {
        const int slot = st & 3;
        const uint32_t smA = smb + slot * STG;
        const uint32_t smB = smA + ASTG;
        const int k0 = st * 32;
        {
            const int m = tid >> 2, u = tid & 3;
            cp_async16(smA + m * 64 + ((u ^ (m & 3)) * 16),
                       Abase + (size_t)m * 256 + k0 + u * 8);
        }
        const char* bsrc = (const char*)(Bbase + (size_t)st * 2048);
#pragma unroll
        for (int i = 0; i < 2; i++) {
            const int idx = tid + i * 256;
            cp_async16(smB + idx * 16, bsrc + (size_t)idx * 16);
        }
        CP_COMMIT();
    };

    issue(0); issue(1); issue(2);

    float acc[2][4][4] = {};

#pragma unroll 1
    for (int st = 0; st < 8; st++) {
        if (st + 3 < 8) issue(st + 3);
        if (st < 5)       asm volatile("cp.async.wait_group 3;" ::: "memory");
        else if (st == 5) asm volatile("cp.async.wait_group 2;" ::: "memory");
        else if (st == 6) asm volatile("cp.async.wait_group 1;" ::: "memory");
        else              asm volatile("cp.async.wait_group 0;" ::: "memory");
        __syncthreads();

        const int slot = st & 3;
        const uint32_t smA = smb + slot * STG;
        const uint32_t smB = smA + ASTG;

#pragma unroll
        for (int tk = 0; tk < 2; tk++) {
            unsigned af[2][4];
            const uint32_t uphys = (uint32_t)((tk * 2 + uoff) ^ s3) * 16;
#pragma unroll
            for (int tm = 0; tm < 2; tm++)
                LDSM_X4(af[tm], smA + (uint32_t)(rbase + tm * 16) * 64 + uphys);

            unsigned bf[4][2];
#pragma unroll
            for (int tn = 0; tn < 4; tn++) {
                const int widx = (((wn >> 3) + tn) * 2 + tk) * 32 + lane;
                asm("ld.shared.v2.b32 {%0,%1}, [%2];"
                    : "=r"(bf[tn][0]), "=r"(bf[tn][1]) : "r"(smB + widx * 8));
            }
#pragma unroll
            for (int mi = 0; mi < 2; mi++)
#pragma unroll
                for (int ni = 0; ni < 4; ni++)
                    mma_f16(acc[mi][ni], af[mi], bf[ni]);
        }
        __syncthreads();
    }

    // epilogue
#pragma unroll
    for (int mi = 0; mi < 2; mi++) {
        const int r = mt * MT + wm + mi * 16 + (lane >> 2);
#pragma unroll
        for (int ni = 0; ni < 4; ni++) {
            const int c = nt * 128 + wn + ni * 8 + (lane & 3) * 2;
            const float2 bv = *(const float2*)&bias[c];
            const float o0x = acc[mi][ni][0] + bv.x;
            const float o0y = acc[mi][ni][1] + bv.y;
            const float o1x = acc[mi][ni][2] + bv.x;
            const float o1y = acc[mi][ni][3] + bv.y;
            if (omode == 2) {
                // head-major fp16: [b][h][lv][32]
                __half* CH = (__half*)C;
                const int hh = c >> 5, ch = c & 31;
                const int r0 = r, r1 = r + 8;
                const size_t off0 = ((size_t)((r0 / LQ) * NH + hh) * LQ + (r0 % LQ)) * 32 + ch;
                const size_t off1 = ((size_t)((r1 / LQ) * NH + hh) * LQ + (r1 % LQ)) * 32 + ch;
                *(uint32_t*)&CH[off0] = packh2(o0x, o0y);
                *(uint32_t*)&CH[off1] = packh2(o1x, o1y);
            } else {
                float* CF = (float*)C;
                *(float2*)&CF[(size_t)r * N + c]       = make_float2(o0x, o0y);
                *(float2*)&CF[(size_t)(r + 8) * N + c] = make_float2(o1x, o1y);
            }
        }
    }
}

// ---------------------------------------------------------------------------
// Deformable sampling — warp = (query, head-pair). Lanes 0-15 build head h0's
// taps, lanes 16-31 head h1's. Gather interleaves both heads (MLP 16).
// Folded reduction: head dim -> lane bit4 first, then xor strides 4, 8.
// ---------------------------------------------------------------------------
__global__ __launch_bounds__(256, 6) void ms_sample_kernel(
    const float* __restrict__ refp)   // [B, Lq, 4, 2]
{
    const int t    = threadIdx.x;
    const int warp = t >> 5;
    const int lid  = t & 31;
    const int qi   = blockIdx.x * 2 + (warp >> 2);
    const int b    = blockIdx.y;
    const int bq   = b * LQ + qi;
    const int wh   = warp & 3;        // head pair: heads 2*wh, 2*wh+1
    const int hw   = lid >> 4;        // which head within pair
    const int h    = wh * 2 + hw;
    const int lp   = lid & 15;        // (level, point)

    __shared__ int2 s_tap[8][2][64];  // [warp][head-in-pair][tap] {byte_off, w}

    // --- fused softmax + tap build, both half-warps active
    {
        const float logit = g_offattn[(size_t)bq * NFUSE + 256 + h * 16 + lp];
        float m = logit;
#pragma unroll
        for (int o = 8; o; o >>= 1) m = fmaxf(m, __shfl_xor_sync(0xFFFFFFFFu, m, o));
        const float e = __expf(logit - m);
        float ssum = e;
#pragma unroll
        for (int o = 8; o; o >>= 1) ssum += __shfl_xor_sync(0xFFFFFFFFu, ssum, o);
        const float aw = e / ssum;

        const int l = lp >> 2;
        const int W = 64 >> l;
        const int start = (l == 0) ? 0 : (l == 1) ? 4096 : (l == 2) ? 5120 : 5376;

        const float rx = refp[((size_t)bq * 4 + l) * 2 + 0];
        const float ry = refp[((size_t)bq * 4 + l) * 2 + 1];
        const float* op = g_offattn + (size_t)bq * NFUSE + h * 32 + lp * 2;

        const float x = fmaf(rx, (float)W, op[0]) - 0.5f;
        const float y = fmaf(ry, (float)W, op[1]) - 0.5f;
        const float x0f = floorf(x), y0f = floorf(y);
        const int x0 = (int)x0f, y0 = (int)y0f;
        const float wx = x - x0f, wy = y - y0f;

        const bool xi0 = (x0 >= 0) && (x0 < W);
        const bool xi1 = (x0 + 1 >= 0) && (x0 + 1 < W);
        const bool yi0 = (y0 >= 0) && (y0 < W);
        const bool yi1 = (y0 + 1 >= 0) && (y0 + 1 < W);

        const int base = (start + y0 * W + x0) * 64;   // byte offset (64B/row)
        const int wb   = W * 64;
        int2* tp = &s_tap[warp][hw][lp * 4];
        bool v;
        v = xi0 && yi0;
        tp[0] = make_int2(v ? base : 0,           __float_as_int(v ? aw * (1.f - wx) * (1.f - wy) : 0.f));
        v = xi1 && yi0;
        tp[1] = make_int2(v ? base + 64 : 0,      __float_as_int(v ? aw * wx * (1.f - wy) : 0.f));
        v = xi0 && yi1;
        tp[2] = make_int2(v ? base + wb : 0,      __float_as_int(v ? aw * (1.f - wx) * wy : 0.f));
        v = xi1 && yi1;
        tp[3] = make_int2(v ? base + wb + 64 : 0, __float_as_int(v ? aw * wx * wy : 0.f));
    }
    __syncwarp();

    // --- interleaved gather for both heads (sub-slot = lid>>2: 8 taps/instr)
    const int sub = lid >> 2;
    const int cb  = (lid & 3) * 16;   // byte offset of channel octet
    const char* vb0 = (const char*)(g_vprojH + ((size_t)(b * NH + wh * 2) * LQ) * 32) + cb;
    const char* vb1 = vb0 + (size_t)LQ * 64;
    const int2* t0 = s_tap[warp][0];
    const int2* t1 = s_tap[warp][1];

    float a[8] = {}, c[8] = {};
#pragma unroll
    for (int j = 0; j < 8; j++) {
        const int2 tv0 = t0[j * 8 + sub];
        const int2 tv1 = t1[j * 8 + sub];
        const float w0 = __int_as_float(tv0.y);
        const float w1 = __int_as_float(tv1.y);
        const uint4 v0 = *(const uint4*)(vb0 + tv0.x);
        const uint4 v1 = *(const uint4*)(vb1 + tv1.x);
        const float2 p0 = __half22float2(*(const __half2*)&v0.x);
        const float2 p1 = __half22float2(*(const __half2*)&v0.y);
        const float2 p2 = __half22float2(*(const __half2*)&v0.z);
        const float2 p3 = __half22float2(*(const __half2*)&v0.w);
        a[0] = fmaf(w0, p0.x, a[0]); a[1] = fmaf(w0, p0.y, a[1]);
        a[2] = fmaf(w0, p1.x, a[2]); a[3] = fmaf(w0, p1.y, a[3]);
        a[4] = fmaf(w0, p2.x, a[4]); a[5] = fmaf(w0, p2.y, a[5]);
        a[6] = fmaf(w0, p3.x, a[6]); a[7] = fmaf(w0, p3.y, a[7]);
        const float2 q0 = __half22float2(*(const __half2*)&v1.x);
        const float2 q1 = __half22float2(*(const __half2*)&v1.y);
        const float2 q2 = __half22float2(*(const __half2*)&v1.z);
        const float2 q3 = __half22float2(*(const __half2*)&v1.w);
        c[0] = fmaf(w1, q0.x, c[0]); c[1] = fmaf(w1, q0.y, c[1]);
        c[2] = fmaf(w1, q1.x, c[2]); c[3] = fmaf(w1, q1.y, c[3]);
        c[4] = fmaf(w1, q2.x, c[4]); c[5] = fmaf(w1, q2.y, c[5]);
        c[6] = fmaf(w1, q3.x, c[6]); c[7] = fmaf(w1, q3.y, c[7]);
    }

    // fold head dim into lane bit4, then reduce strides 4, 8
#pragma unroll
    for (int k = 0; k < 8; k++) {
        const float ax = a[k] + __shfl_xor_sync(0xFFFFFFFFu, a[k], 16);
        const float cx = c[k] + __shfl_xor_sync(0xFFFFFFFFu, c[k], 16);
        a[k] = (lid < 16) ? ax : cx;
    }
#pragma unroll
    for (int o = 4; o <= 8; o <<= 1)
#pragma unroll
        for (int k = 0; k < 8; k++)
            a[k] += __shfl_xor_sync(0xFFFFFFFFu, a[k], o);

    if ((lid & 12) == 0) {
        const int hcur = wh * 2 + (lid >> 4);
        const int ch   = (lid & 3) * 8;
        uint4 o;
        o.x = packh2(a[0], a[1]);
        o.y = packh2(a[2], a[3]);
        o.z = packh2(a[4], a[5]);
        o.w = packh2(a[6], a[7]);
        *(uint4*)&g_accH[(size_t)bq * CD + hcur * HD + ch] = o;
    }
}

// ---------------------------------------------------------------------------
// kernel_launch
// Inputs: query, reference_points, value, W_off, b_off, W_attn, b_attn,
//         W_val, b_val, W_out, b_out
// ---------------------------------------------------------------------------
extern "C" void kernel_launch(void* const* d_in, const int* in_sizes, int n_in,
                              void* d_out, int out_size)
{
    const float* query = (const float*)d_in[0];
    const float* refp  = (const float*)d_in[1];
    const float* value = (const float*)d_in[2];
    const float* W_off = (const float*)d_in[3];
    const float* b_off = (const float*)d_in[4];
    const float* W_at  = (const float*)d_in[5];
    const float* b_at  = (const float*)d_in[6];
    const float* W_val = (const float*)d_in[7];
    const float* b_val = (const float*)d_in[8];
    const float* W_out = (const float*)d_in[9];
    const float* b_out = (const float*)d_in[10];
    float* out = (float*)d_out;

    float *offattn, *bf;
    __half *vprojh, *qh, *vh, *acch;
    uint32_t *bpv, *bpf, *bpo;
    cudaGetSymbolAddress((void**)&vprojh,  g_vprojH);
    cudaGetSymbolAddress((void**)&offattn, g_offattn);
    cudaGetSymbolAddress((void**)&qh,      g_qH);
    cudaGetSymbolAddress((void**)&vh,      g_vH);
    cudaGetSymbolAddress((void**)&acch,    g_accH);
    cudaGetSymbolAddress((void**)&bf,      g_bf);
    cudaGetSymbolAddress((void**)&bpv,     g_BpV);
    cudaGetSymbolAddress((void**)&bpf,     g_BpF);
    cudaGetSymbolAddress((void**)&bpo,     g_BpO);

    dim3 blk(256);

    prep<<<(CONV_N + 114688) / 256, blk>>>((const float4*)query, (const float4*)value,
                                           W_off, b_off, W_at, b_at, W_val, W_out);
    // fused: V-proj (2 n-tiles, fp16 head-major out) + offattn-proj (3 n-tiles, fp32)
    gemm_f16<2, 0><<<dim3(5, MROWS / 64), blk>>>(vh, bpv, b_val, vprojh, 256, 2,
                                                 qh, bpf, bf, offattn, NFUSE);
    ms_sample_kernel<<<dim3(LQ / 2, NB), blk>>>(refp);
    gemm_f16<0, 0><<<dim3(2, MROWS / 64), blk>>>(acch, bpo, b_out, out, 256, 2,
                                                 acch, bpo, b_out, out, 256);
}